// round 5
// baseline (speedup 1.0000x reference)
#include <cuda_runtime.h>
#include <cuda_bf16.h>
#include <math.h>

// Problem constants
#define BB 2
#define CC 64
#define HH 192
#define WW 192
#define HP 194   // padded
#define NTAP 9

typedef unsigned long long u64;

// ---------------- f32x2 packed helpers --------------------------------------
__device__ __forceinline__ u64 dup2(float x) {
    u64 r; asm("mov.b64 %0, {%1,%1};" : "=l"(r) : "f"(x)); return r;
}
__device__ __forceinline__ u64 pk2(float lo, float hi) {
    u64 r; asm("mov.b64 %0, {%1,%2};" : "=l"(r) : "f"(lo), "f"(hi)); return r;
}
__device__ __forceinline__ void fma2(u64 &d, u64 a, u64 b) {
    asm("fma.rn.f32x2 %0, %1, %2, %0;" : "+l"(d) : "l"(a), "l"(b));
}
__device__ __forceinline__ float2 unpk(u64 v) {
    float2 f; asm("mov.b64 {%0,%1}, %2;" : "=f"(f.x), "=f"(f.y) : "l"(v)); return f;
}

// ---------------- scratch buffers (static device memory; no allocation) -----
__device__ float g_frpad[BB * CC * HP * HP];
__device__ float g_offset[BB * 18 * HH * WW];
__device__ float g_x[BB * CC * HH * WW];
__device__ float g_y[BB * CC * HH * WW];
__device__ float g_t1[BB * CC * 190 * 190];

// ---------------- pad kernel -------------------------------------------------
__global__ void pad_kernel(const float* __restrict__ src, float* __restrict__ dst) {
    int idx = blockIdx.x * blockDim.x + threadIdx.x;
    int total = BB * CC * HP * HP;
    if (idx >= total) return;
    int c2 = idx % HP;
    int r2 = (idx / HP) % HP;
    int bc = idx / (HP * HP);
    float v = 0.f;
    if (r2 >= 1 && r2 <= HH && c2 >= 1 && c2 <= WW)
        v = src[(size_t)bc * HH * WW + (r2 - 1) * WW + (c2 - 1)];
    dst[idx] = v;
}

// ---------------- generic 3x3 conv (kept for pconv, COUT=18) -----------------
template<int CIN, int COUT, int PADV, bool HAS_IN2>
__global__ void __launch_bounds__(256, 1)
conv3x3_kernel(const float* __restrict__ inA, const float* __restrict__ inB,
               const float* __restrict__ w, const float* __restrict__ bias,
               const float* __restrict__ res, float* __restrict__ out,
               int Hin, int Win, int Hout, int Wout)
{
    constexpr int CH = 8;
    constexpr int COUT_P = (COUT + 3) & ~3;
    __shared__ __align__(16) float sIn[CH][18][18];
    __shared__ __align__(16) float sW[CH * 9 * COUT_P];

    const int b   = blockIdx.z;
    const int ty0 = blockIdx.y * 16;
    const int tx0 = blockIdx.x * 16;
    const int tid = threadIdx.x;
    const int py = tid >> 4, px = tid & 15;
    const int oy = ty0 + py, ox = tx0 + px;

    float acc[COUT_P];
#pragma unroll
    for (int i = 0; i < COUT_P; i++) acc[i] = 0.f;

    const int cstride = HAS_IN2 ? 64 : CIN;

    for (int c0 = 0; c0 < CIN; c0 += CH) {
        for (int idx = tid; idx < CH * 18 * 18; idx += 256) {
            int c   = idx / (18 * 18);
            int rem = idx % (18 * 18);
            int r = rem / 18, cc = rem % 18;
            int iy = ty0 - PADV + r;
            int ix = tx0 - PADV + cc;
            float v = 0.f;
            if (iy >= 0 && iy < Hin && ix >= 0 && ix < Win) {
                int ci = c0 + c;
                const float* src = inA;
                int cl = ci;
                if (HAS_IN2 && ci >= 64) { src = inB; cl = ci - 64; }
                v = src[(((size_t)b * cstride + cl) * Hin + iy) * Win + ix];
            }
            sIn[c][r][cc] = v;
        }
        for (int idx = tid; idx < CH * 9 * COUT_P; idx += 256) {
            int co = idx % COUT_P;
            int ck = idx / COUT_P;
            int ci_l = ck / 9, k = ck % 9;
            float v = 0.f;
            if (co < COUT) v = w[((size_t)co * CIN + (c0 + ci_l)) * 9 + k];
            sW[idx] = v;
        }
        __syncthreads();

        for (int ci = 0; ci < CH; ci++) {
#pragma unroll
            for (int ky = 0; ky < 3; ky++) {
#pragma unroll
                for (int kx = 0; kx < 3; kx++) {
                    float xv = sIn[ci][py + ky][px + kx];
                    const float4* wp = reinterpret_cast<const float4*>(
                        &sW[(ci * 9 + ky * 3 + kx) * COUT_P]);
#pragma unroll
                    for (int j = 0; j < COUT_P / 4; j++) {
                        float4 w4 = wp[j];
                        acc[4 * j + 0] = fmaf(w4.x, xv, acc[4 * j + 0]);
                        acc[4 * j + 1] = fmaf(w4.y, xv, acc[4 * j + 1]);
                        acc[4 * j + 2] = fmaf(w4.z, xv, acc[4 * j + 2]);
                        acc[4 * j + 3] = fmaf(w4.w, xv, acc[4 * j + 3]);
                    }
                }
            }
        }
        __syncthreads();
    }

    if (oy < Hout && ox < Wout) {
        size_t obase = (size_t)b * COUT * Hout * Wout + (size_t)oy * Wout + ox;
        size_t cs = (size_t)Hout * Wout;
#pragma unroll
        for (int co = 0; co < COUT; co++) {
            float v = acc[co];
            if (bias) v += bias[co];
            if (res)  v += res[obase + co * cs];
            out[obase + co * cs] = v;
        }
    }
}

// ---------------- FFMA2 weight-stationary 3x3 conv, COUT=64 ------------------
// 512 threads = 8 cout-groups (8 couts each) x 64 px-threads (8 px each).
// Each thread: 8 contiguous pixels x 8 output channels = 32 f32x2 accs.
// Tile: 16 rows x 32 cols. Weights loaded once per (ci,tap) into regs and
// reused across the 8 pixels -> weight LDS per ci drops 72 -> 18.
template<int CIN, int PADV, bool HAS_IN2>
__global__ void __launch_bounds__(512, 1)
conv3x3_f2_kernel(const float* __restrict__ inA, const float* __restrict__ inB,
                  const float* __restrict__ w, const float* __restrict__ bias,
                  const float* __restrict__ res, float* __restrict__ out,
                  int Hin, int Win, int Hout, int Wout)
{
    constexpr int CH = 8;
    __shared__ __align__(16) float sIn[CH][18][36];   // rows 18, cols 34 used
    __shared__ __align__(16) float sW[CH][9][64];     // [ci][tap][co]

    const int b   = blockIdx.z;
    const int ty0 = blockIdx.y * 16;
    const int tx0 = blockIdx.x * 32;
    const int tid = threadIdx.x;
    const int g   = tid >> 6;           // cout group 0..7 -> couts g*8..g*8+7
    const int t   = tid & 63;
    const int qy  = t >> 2;             // 0..15 (output row)
    const int c0  = (t & 3) * 8;        // 0,8,16,24 (output col base, 8 px)

    u64 acc[8][4];
#pragma unroll
    for (int p = 0; p < 8; p++)
#pragma unroll
        for (int j = 0; j < 4; j++) acc[p][j] = 0ull;

    const int cstride = HAS_IN2 ? 64 : CIN;

    for (int cc0 = 0; cc0 < CIN; cc0 += CH) {
        // stage input tile
        for (int idx = tid; idx < CH * 18 * 36; idx += 512) {
            int c   = idx / 648;
            int rem = idx % 648;
            int r = rem / 36, cc = rem % 36;
            int iy = ty0 - PADV + r;
            int ix = tx0 - PADV + cc;
            float v = 0.f;
            if (cc < 34 && iy >= 0 && iy < Hin && ix >= 0 && ix < Win) {
                int ci = cc0 + c;
                const float* src = inA;
                int cl = ci;
                if (HAS_IN2 && ci >= 64) { src = inB; cl = ci - 64; }
                v = src[(((size_t)b * cstride + cl) * Hin + iy) * Win + ix];
            }
            (&sIn[0][0][0])[idx] = v;
        }
        // stage weights [ci][tap][co]
        for (int idx = tid; idx < CH * 9 * 64; idx += 512) {
            int co = idx & 63;
            int ck = idx >> 6;
            int ci = ck / 9, k = ck % 9;
            (&sW[0][0][0])[idx] = w[((size_t)co * CIN + (cc0 + ci)) * 9 + k];
        }
        __syncthreads();

#pragma unroll 1
        for (int ci = 0; ci < CH; ci++) {
#pragma unroll
            for (int ky = 0; ky < 3; ky++) {
                // load input row qy+ky, cols c0..c0+9, duplicate into f32x2
                const float* rowp = &sIn[ci][qy + ky][c0];
                float4 ra = *reinterpret_cast<const float4*>(rowp);
                float4 rb = *reinterpret_cast<const float4*>(rowp + 4);
                float2 rc = *reinterpret_cast<const float2*>(rowp + 8);
                u64 din[10];
                din[0] = dup2(ra.x); din[1] = dup2(ra.y);
                din[2] = dup2(ra.z); din[3] = dup2(ra.w);
                din[4] = dup2(rb.x); din[5] = dup2(rb.y);
                din[6] = dup2(rb.z); din[7] = dup2(rb.w);
                din[8] = dup2(rc.x); din[9] = dup2(rc.y);
#pragma unroll
                for (int kx = 0; kx < 3; kx++) {
                    const ulonglong2* wp = reinterpret_cast<const ulonglong2*>(
                        &sW[ci][ky * 3 + kx][g * 8]);
                    ulonglong2 w01 = wp[0];
                    ulonglong2 w23 = wp[1];
#pragma unroll
                    for (int p = 0; p < 8; p++) {
                        u64 xv = din[p + kx];
                        fma2(acc[p][0], xv, w01.x);
                        fma2(acc[p][1], xv, w01.y);
                        fma2(acc[p][2], xv, w23.x);
                        fma2(acc[p][3], xv, w23.y);
                    }
                }
            }
        }
        __syncthreads();
    }

    // store: 8 px x 8 couts per thread
    size_t cs = (size_t)Hout * Wout;
    int oy = ty0 + qy;
    if (oy < Hout) {
#pragma unroll
        for (int p = 0; p < 8; p++) {
            int ox = tx0 + c0 + p;
            if (ox < Wout) {
                size_t base = (size_t)b * 64 * cs + (size_t)oy * Wout + ox;
#pragma unroll
                for (int j = 0; j < 4; j++) {
                    float2 v = unpk(acc[p][j]);
                    int co = g * 8 + 2 * j;
                    float o0 = v.x, o1 = v.y;
                    if (bias) { o0 += bias[co]; o1 += bias[co + 1]; }
                    if (res)  { o0 += res[base + (size_t)co * cs];
                                o1 += res[base + (size_t)(co + 1) * cs]; }
                    out[base + (size_t)co * cs]       = o0;
                    out[base + (size_t)(co + 1) * cs] = o1;
                }
            }
        }
    }
}

// ---------------- deformable conv, FFMA2, 512-thread --------------------------
__global__ void __launch_bounds__(512, 1)
deform_f2_kernel(const float* __restrict__ xpad,    // (B,64,194,194)
                 const float* __restrict__ offset,  // (B,18,192,192)
                 const float* __restrict__ wdc,     // (64,64,3,3)
                 float* __restrict__ out)           // (B,64,192,192)
{
    __shared__ __align__(16) float sW[64 * 64];  // [ci][co] for current tap

    const int b   = blockIdx.z;
    const int ty0 = blockIdx.y * 16;
    const int tx0 = blockIdx.x * 32;
    const int tid = threadIdx.x;
    const int py  = tid >> 5, px = tid & 31;
    const int i   = ty0 + py;
    const int j   = tx0 + px;

    u64 acc[32];
#pragma unroll
    for (int c = 0; c < 32; c++) acc[c] = 0ull;

    for (int n = 0; n < NTAP; n++) {
        __syncthreads();
        for (int idx = tid; idx < 4096; idx += 512) {
            int ci = idx >> 6, co = idx & 63;
            sW[idx] = wdc[((size_t)co * 64 + ci) * 9 + n];
        }
        __syncthreads();

        int dr = n / 3 - 1, dc = n % 3 - 1;
        float offr = offset[(((size_t)b * 18 + n) * HH + i) * WW + j];
        float offc = offset[(((size_t)b * 18 + 9 + n) * HH + i) * WW + j];
        float p_r = (float)(i + 1 + dr) + offr;
        float p_c = (float)(j + 1 + dc) + offc;
        float pr = fminf(fmaxf(p_r, 0.f), 193.f);
        float pc = fminf(fmaxf(p_c, 0.f), 193.f);
        float fr = floorf(p_r), fc = floorf(p_c);
        float qr0 = fminf(fmaxf(fr,       0.f), 193.f);
        float qc0 = fminf(fmaxf(fc,       0.f), 193.f);
        float qr1 = fminf(fmaxf(fr + 1.f, 0.f), 193.f);
        float qc1 = fminf(fmaxf(fc + 1.f, 0.f), 193.f);
        float glt = (1.f + (qr0 - pr)) * (1.f + (qc0 - pc));
        float grb = (1.f - (qr1 - pr)) * (1.f - (qc1 - pc));
        float glb = (1.f + (qr0 - pr)) * (1.f - (qc1 - pc));
        float grt = (1.f - (qr1 - pr)) * (1.f + (qc0 - pc));
        int i00 = (int)qr0 * HP + (int)qc0;
        int i11 = (int)qr1 * HP + (int)qc1;
        int i01 = (int)qr0 * HP + (int)qc1;
        int i10 = (int)qr1 * HP + (int)qc0;

        const float* xb = xpad + (size_t)b * 64 * HP * HP;
#pragma unroll 1
        for (int ci = 0; ci < 64; ci++) {
            const float* xc = xb + (size_t)ci * HP * HP;
            float xo = glt * xc[i00] + grb * xc[i11]
                     + glb * xc[i01] + grt * xc[i10];
            u64 x2 = dup2(xo);
            const ulonglong2* wp = reinterpret_cast<const ulonglong2*>(&sW[ci * 64]);
#pragma unroll
            for (int jj = 0; jj < 16; jj++) {
                ulonglong2 q = wp[jj];
                fma2(acc[2 * jj],     x2, q.x);
                fma2(acc[2 * jj + 1], x2, q.y);
            }
        }
    }

    size_t obase = (size_t)b * 64 * HH * WW + (size_t)i * WW + j;
#pragma unroll
    for (int jj = 0; jj < 32; jj++) {
        float2 v = unpk(acc[jj]);
        out[obase + (size_t)(2 * jj)     * HH * WW] = v.x;
        out[obase + (size_t)(2 * jj + 1) * HH * WW] = v.y;
    }
}

// ---------------- GDN + celu (in place), FFMA2 -------------------------------
__global__ void __launch_bounds__(256, 1)
gdn_celu_kernel(float* __restrict__ x, const float* __restrict__ beta,
                const float* __restrict__ gamma, int HWp)
{
    __shared__ __align__(16) float sG[64 * 64];  // sG[ci*64+co] = gamma[co][ci]
    __shared__ float sB[64];
    const int tid = threadIdx.x;
    for (int idx = tid; idx < 4096; idx += 256) {
        int co = idx & 63, ci = idx >> 6;
        sG[idx] = gamma[co * 64 + ci];
    }
    if (tid < 64) sB[tid] = beta[tid];
    __syncthreads();

    int p = blockIdx.x * 256 + tid;
    if (p >= BB * HWp) return;
    int b = p / HWp, hw = p % HWp;
    float* base = x + (size_t)b * 64 * HWp + hw;

    u64 nrm[32];
#pragma unroll
    for (int jj = 0; jj < 32; jj++) nrm[jj] = pk2(sB[2 * jj], sB[2 * jj + 1]);

    for (int ci = 0; ci < 64; ci++) {
        float v = base[(size_t)ci * HWp];
        u64 sq = dup2(v * v);
        const ulonglong2* gp = reinterpret_cast<const ulonglong2*>(&sG[ci * 64]);
#pragma unroll
        for (int jj = 0; jj < 16; jj++) {
            ulonglong2 q = gp[jj];
            fma2(nrm[2 * jj],     sq, q.x);
            fma2(nrm[2 * jj + 1], sq, q.y);
        }
    }
#pragma unroll
    for (int jj = 0; jj < 32; jj++) {
        float2 nv = unpk(nrm[jj]);
        float v0 = base[(size_t)(2 * jj) * HWp];
        float v1 = base[(size_t)(2 * jj + 1) * HWp];
        float t0 = v0 * rsqrtf(nv.x);
        float t1 = v1 * rsqrtf(nv.y);
        base[(size_t)(2 * jj) * HWp]     = (t0 > 0.f) ? t0 : expm1f(t0);
        base[(size_t)(2 * jj + 1) * HWp] = (t1 > 0.f) ? t1 : expm1f(t1);
    }
}

// ---------------- final add --------------------------------------------------
__global__ void add_kernel(const float* __restrict__ a, const float* __restrict__ b,
                           float* __restrict__ out, int n)
{
    int i = blockIdx.x * blockDim.x + threadIdx.x;
    if (i < n) out[i] = a[i] + b[i];
}

// ---------------- launcher ---------------------------------------------------
extern "C" void kernel_launch(void* const* d_in, const int* in_sizes, int n_in,
                              void* d_out, int out_size)
{
    const float* f_r     = (const float*)d_in[0];
    const float* m_t     = (const float*)d_in[1];
    const float* w_pconv = (const float*)d_in[2];
    const float* b_pconv = (const float*)d_in[3];
    const float* w_dc    = (const float*)d_in[4];
    const float* w_cat   = (const float*)d_in[5];
    const float* b_cat   = (const float*)d_in[6];
    const float* rb_w1   = (const float*)d_in[7];
    const float* rb_w2   = (const float*)d_in[8];
    const float* rb_beta = (const float*)d_in[9];
    const float* rb_gamma= (const float*)d_in[10];
    float* out = (float*)d_out;

    float *frpad, *offs, *xbuf, *ybuf, *t1;
    cudaGetSymbolAddress((void**)&frpad, g_frpad);
    cudaGetSymbolAddress((void**)&offs,  g_offset);
    cudaGetSymbolAddress((void**)&xbuf,  g_x);
    cudaGetSymbolAddress((void**)&ybuf,  g_y);
    cudaGetSymbolAddress((void**)&t1,    g_t1);

    // 1. pad f_r
    {
        int total = BB * CC * HP * HP;
        pad_kernel<<<(total + 255) / 256, 256>>>(f_r, frpad);
    }
    // 2. offset = pconv(m_t), pad 1, 64->18
    {
        dim3 grid(12, 12, BB);
        conv3x3_kernel<64, 18, 1, false><<<grid, 256>>>(
            m_t, nullptr, w_pconv, b_pconv, nullptr, offs, HH, WW, HH, WW);
    }
    // 3. x = deform_conv(f_r, offset, w_dc)
    {
        dim3 grid(6, 12, BB);
        deform_f2_kernel<<<grid, 512>>>(frpad, offs, w_dc, xbuf);
    }
    // 4. y = conv(cat[x, f_r]), pad 1, 128->64
    {
        dim3 grid(6, 12, BB);
        conv3x3_f2_kernel<128, 1, true><<<grid, 512>>>(
            xbuf, f_r, w_cat, b_cat, nullptr, ybuf, HH, WW, HH, WW);
    }
    // 5. resblocks
    for (int l = 0; l < 3; l++) {
        const float* w1 = rb_w1 + (size_t)l * 64 * 64 * 9;
        const float* w2 = rb_w2 + (size_t)l * 64 * 64 * 9;
        const float* bt = rb_beta + (size_t)l * 64;
        const float* gm = rb_gamma + (size_t)l * 64 * 64;
        // conv1: pad 0, 192 -> 190
        {
            dim3 grid(6, 12, BB);
            conv3x3_f2_kernel<64, 0, false><<<grid, 512>>>(
                ybuf, nullptr, w1, nullptr, nullptr, t1, HH, WW, 190, 190);
        }
        // gdn + celu in place on t1
        {
            int HWp = 190 * 190;
            int total = BB * HWp;
            gdn_celu_kernel<<<(total + 255) / 256, 256>>>(t1, bt, gm, HWp);
        }
        // conv2: pad 2, 190 -> 192, + residual y (in place into y)
        {
            dim3 grid(6, 12, BB);
            conv3x3_f2_kernel<64, 2, false><<<grid, 512>>>(
                t1, nullptr, w2, nullptr, ybuf, ybuf, 190, 190, HH, WW);
        }
    }
    // 6. out = y + x
    {
        int n = BB * CC * HH * WW;
        add_kernel<<<(n + 255) / 256, 256>>>(ybuf, xbuf, out, n);
    }
}

// round 7
// speedup vs baseline: 1.6687x; 1.6687x over previous
#include <cuda_runtime.h>
#include <cuda_bf16.h>
#include <math.h>
#include <stdint.h>

// Problem constants
#define BB 2
#define CC 64
#define HH 192
#define WW 192
#define HP 194   // padded
#define NTAP 9

typedef unsigned long long u64;
typedef unsigned int u32;

// ---------------- f32x2 packed helpers --------------------------------------
__device__ __forceinline__ u64 dup2(float x) {
    u64 r; asm("mov.b64 %0, {%1,%1};" : "=l"(r) : "f"(x)); return r;
}
__device__ __forceinline__ u64 pk2(float lo, float hi) {
    u64 r; asm("mov.b64 %0, {%1,%2};" : "=l"(r) : "f"(lo), "f"(hi)); return r;
}
__device__ __forceinline__ void fma2(u64 &d, u64 a, u64 b) {
    asm("fma.rn.f32x2 %0, %1, %2, %0;" : "+l"(d) : "l"(a), "l"(b));
}
__device__ __forceinline__ float2 unpk(u64 v) {
    float2 f; asm("mov.b64 {%0,%1}, %2;" : "=f"(f.x), "=f"(f.y) : "l"(v)); return f;
}

// ---------------- cp.async helpers -------------------------------------------
__device__ __forceinline__ void cpa4(u32 saddr, const void* g, int sz) {
    asm volatile("cp.async.ca.shared.global [%0], [%1], 4, %2;"
                 :: "r"(saddr), "l"(g), "r"(sz));
}
__device__ __forceinline__ void cpa_commit() {
    asm volatile("cp.async.commit_group;");
}
__device__ __forceinline__ void cpa_wait1() {
    asm volatile("cp.async.wait_group 1;");
}

// ---------------- scratch buffers (static device memory; no allocation) -----
__device__ float g_frpad[BB * CC * HP * HP];
__device__ float g_offset[BB * 18 * HH * WW];
__device__ float g_x[BB * CC * HH * WW];
__device__ float g_y[BB * CC * HH * WW];
__device__ float g_t1[BB * CC * 190 * 190];

// ---------------- pad kernel -------------------------------------------------
__global__ void pad_kernel(const float* __restrict__ src, float* __restrict__ dst) {
    int idx = blockIdx.x * blockDim.x + threadIdx.x;
    int total = BB * CC * HP * HP;
    if (idx >= total) return;
    int c2 = idx % HP;
    int r2 = (idx / HP) % HP;
    int bc = idx / (HP * HP);
    float v = 0.f;
    if (r2 >= 1 && r2 <= HH && c2 >= 1 && c2 <= WW)
        v = src[(size_t)bc * HH * WW + (r2 - 1) * WW + (c2 - 1)];
    dst[idx] = v;
}

// ---------------- generic 3x3 conv (kept for pconv, COUT=18) -----------------
template<int CIN, int COUT, int PADV, bool HAS_IN2>
__global__ void __launch_bounds__(256, 1)
conv3x3_kernel(const float* __restrict__ inA, const float* __restrict__ inB,
               const float* __restrict__ w, const float* __restrict__ bias,
               const float* __restrict__ res, float* __restrict__ out,
               int Hin, int Win, int Hout, int Wout)
{
    constexpr int CH = 8;
    constexpr int COUT_P = (COUT + 3) & ~3;
    __shared__ __align__(16) float sIn[CH][18][18];
    __shared__ __align__(16) float sW[CH * 9 * COUT_P];

    const int b   = blockIdx.z;
    const int ty0 = blockIdx.y * 16;
    const int tx0 = blockIdx.x * 16;
    const int tid = threadIdx.x;
    const int py = tid >> 4, px = tid & 15;
    const int oy = ty0 + py, ox = tx0 + px;

    float acc[COUT_P];
#pragma unroll
    for (int i = 0; i < COUT_P; i++) acc[i] = 0.f;

    const int cstride = HAS_IN2 ? 64 : CIN;

    for (int c0 = 0; c0 < CIN; c0 += CH) {
        for (int idx = tid; idx < CH * 18 * 18; idx += 256) {
            int c   = idx / (18 * 18);
            int rem = idx % (18 * 18);
            int r = rem / 18, cc = rem % 18;
            int iy = ty0 - PADV + r;
            int ix = tx0 - PADV + cc;
            float v = 0.f;
            if (iy >= 0 && iy < Hin && ix >= 0 && ix < Win) {
                int ci = c0 + c;
                const float* src = inA;
                int cl = ci;
                if (HAS_IN2 && ci >= 64) { src = inB; cl = ci - 64; }
                v = src[(((size_t)b * cstride + cl) * Hin + iy) * Win + ix];
            }
            sIn[c][r][cc] = v;
        }
        for (int idx = tid; idx < CH * 9 * COUT_P; idx += 256) {
            int co = idx % COUT_P;
            int ck = idx / COUT_P;
            int ci_l = ck / 9, k = ck % 9;
            float v = 0.f;
            if (co < COUT) v = w[((size_t)co * CIN + (c0 + ci_l)) * 9 + k];
            sW[idx] = v;
        }
        __syncthreads();

        for (int ci = 0; ci < CH; ci++) {
#pragma unroll
            for (int ky = 0; ky < 3; ky++) {
#pragma unroll
                for (int kx = 0; kx < 3; kx++) {
                    float xv = sIn[ci][py + ky][px + kx];
                    const float4* wp = reinterpret_cast<const float4*>(
                        &sW[(ci * 9 + ky * 3 + kx) * COUT_P]);
#pragma unroll
                    for (int j = 0; j < COUT_P / 4; j++) {
                        float4 w4 = wp[j];
                        acc[4 * j + 0] = fmaf(w4.x, xv, acc[4 * j + 0]);
                        acc[4 * j + 1] = fmaf(w4.y, xv, acc[4 * j + 1]);
                        acc[4 * j + 2] = fmaf(w4.z, xv, acc[4 * j + 2]);
                        acc[4 * j + 3] = fmaf(w4.w, xv, acc[4 * j + 3]);
                    }
                }
            }
        }
        __syncthreads();
    }

    if (oy < Hout && ox < Wout) {
        size_t obase = (size_t)b * COUT * Hout * Wout + (size_t)oy * Wout + ox;
        size_t cs = (size_t)Hout * Wout;
#pragma unroll
        for (int co = 0; co < COUT; co++) {
            float v = acc[co];
            if (bias) v += bias[co];
            if (res)  v += res[obase + co * cs];
            out[obase + co * cs] = v;
        }
    }
}

// ---------------- FFMA2 3x3 conv, COUT=64, cp.async double-buffered ----------
// R3 compute loop (known good codegen): 512 threads = 2 cout-halves x 256.
// Each thread: 1x2 pixel pair x 32 couts (16 f32x2 accs). Tile 16x32.
// 2-stage cp.async pipeline overlaps chunk c+1 staging with chunk c compute.
// Dynamic SMEM float layout:
//   IN(buf)=buf*5184 : [CH][18][36] (34 cols used)
//   W(buf) =10368+buf*4608 : [CH][9][64]
#define CONV_SMEM_FLOATS (2*5184 + 2*4608)
template<int CIN, int PADV, bool HAS_IN2>
__global__ void __launch_bounds__(512, 1)
conv3x3_f2_kernel(const float* __restrict__ inA, const float* __restrict__ inB,
                  const float* __restrict__ w, const float* __restrict__ bias,
                  const float* __restrict__ res, float* __restrict__ out,
                  int Hin, int Win, int Hout, int Wout)
{
    constexpr int CH = 8;
    constexpr int NC = CIN / CH;
    extern __shared__ __align__(16) float sm[];

    const int b   = blockIdx.z;
    const int ty0 = blockIdx.y * 16;
    const int tx0 = blockIdx.x * 32;
    const int tid = threadIdx.x;
    const int g   = tid >> 8;          // cout half
    const int t   = tid & 255;
    const int qy  = t >> 4;            // 0..15 output row
    const int qx  = t & 15;            // 0..15 output col pair

    const int cstride = HAS_IN2 ? 64 : CIN;
    const u32 smem_base = (u32)__cvta_generic_to_shared(sm);

    // stage chunk (cc0) into buffer buf via cp.async
    auto stage = [&](int buf, int cc0) {
        // input: CH x 18 x 34 region
        for (int idx = tid; idx < CH * 18 * 34; idx += 512) {
            int c   = idx / 612;
            int rem = idx % 612;
            int r = rem / 34, cc = rem % 34;
            int iy = ty0 - PADV + r;
            int ix = tx0 - PADV + cc;
            bool ok = (iy >= 0 && iy < Hin && ix >= 0 && ix < Win);
            int ci = cc0 + c;
            const float* src = inA;
            int cl = ci;
            if (HAS_IN2 && ci >= 64) { src = inB; cl = ci - 64; }
            const float* gp = ok ?
                &src[(((size_t)b * cstride + cl) * Hin + iy) * Win + ix] : src;
            u32 sa = smem_base +
                (u32)(buf * 5184 + (c * 18 + r) * 36 + cc) * 4u;
            cpa4(sa, gp, ok ? 4 : 0);
        }
        // weights: CH x 9 x 64
        for (int idx = tid; idx < CH * 9 * 64; idx += 512) {
            int co = idx & 63;
            int ck = idx >> 6;
            int ci = ck / 9, k = ck % 9;
            const float* gp = &w[((size_t)co * CIN + (cc0 + ci)) * 9 + k];
            u32 sa = smem_base + (u32)(10368 + buf * 4608 + idx) * 4u;
            cpa4(sa, gp, 4);
        }
    };

    u64 acc[2][16];
#pragma unroll
    for (int p = 0; p < 2; p++)
#pragma unroll
        for (int j = 0; j < 16; j++) acc[p][j] = 0ull;

    // prologue: stage chunk 0
    stage(0, 0);
    cpa_commit();

    for (int c = 0; c < NC; c++) {
        int buf = c & 1;
        if (c + 1 < NC) stage(buf ^ 1, (c + 1) * CH);
        cpa_commit();
        cpa_wait1();
        __syncthreads();

        const float* sIn = sm + buf * 5184;          // [CH][18][36]
        const float* sW  = sm + 10368 + buf * 4608;  // [CH][9][64]

#pragma unroll 1
        for (int ci = 0; ci < CH; ci++) {
            u64 d[3][4];
#pragma unroll
            for (int r = 0; r < 3; r++) {
                const float2* ip = reinterpret_cast<const float2*>(
                    &sIn[(ci * 18 + qy + r) * 36 + 2 * qx]);
                float2 a = ip[0], bb = ip[1];
                d[r][0] = dup2(a.x); d[r][1] = dup2(a.y);
                d[r][2] = dup2(bb.x); d[r][3] = dup2(bb.y);
            }
#pragma unroll
            for (int ky = 0; ky < 3; ky++) {
#pragma unroll
                for (int kx = 0; kx < 3; kx++) {
                    u64 xv0 = d[ky][kx];
                    u64 xv1 = d[ky][kx + 1];
                    const ulonglong2* wp = reinterpret_cast<const ulonglong2*>(
                        &sW[(ci * 9 + ky * 3 + kx) * 64 + g * 32]);
#pragma unroll
                    for (int j = 0; j < 8; j++) {
                        ulonglong2 q = wp[j];
                        fma2(acc[0][2 * j],     xv0, q.x);
                        fma2(acc[0][2 * j + 1], xv0, q.y);
                        fma2(acc[1][2 * j],     xv1, q.x);
                        fma2(acc[1][2 * j + 1], xv1, q.y);
                    }
                }
            }
        }
        __syncthreads();
    }

    // store
    size_t cs = (size_t)Hout * Wout;
    int oy = ty0 + qy;
#pragma unroll
    for (int pc = 0; pc < 2; pc++) {
        int ox = tx0 + 2 * qx + pc;
        if (oy < Hout && ox < Wout) {
            size_t base = (size_t)b * 64 * cs + (size_t)oy * Wout + ox;
            u64* ac = acc[pc];
#pragma unroll
            for (int j = 0; j < 16; j++) {
                float2 v = unpk(ac[j]);
                int co = g * 32 + 2 * j;
                float o0 = v.x, o1 = v.y;
                if (bias) { o0 += bias[co]; o1 += bias[co + 1]; }
                if (res)  { o0 += res[base + (size_t)co * cs];
                            o1 += res[base + (size_t)(co + 1) * cs]; }
                out[base + (size_t)co * cs]       = o0;
                out[base + (size_t)(co + 1) * cs] = o1;
            }
        }
    }
}

// ---------------- deformable conv, FFMA2, all-tap weights in SMEM ------------
// Dynamic SMEM: sW[9][64][64] floats = 144KB, loaded once.
#define DEF_SMEM_FLOATS (9 * 64 * 64)
__global__ void __launch_bounds__(512, 1)
deform_f2_kernel(const float* __restrict__ xpad,    // (B,64,194,194)
                 const float* __restrict__ offset,  // (B,18,192,192)
                 const float* __restrict__ wdc,     // (64,64,3,3)
                 float* __restrict__ out)           // (B,64,192,192)
{
    extern __shared__ __align__(16) float sW[];     // [tap][ci][co]

    const int b   = blockIdx.z;
    const int ty0 = blockIdx.y * 16;
    const int tx0 = blockIdx.x * 32;
    const int tid = threadIdx.x;
    const int py  = tid >> 5, px = tid & 31;
    const int i   = ty0 + py;
    const int j   = tx0 + px;

    // stage all weights once: sW[(tap*64+ci)*64+co] = wdc[(co*64+ci)*9+tap]
    for (int idx = tid; idx < 9 * 64 * 64; idx += 512) {
        int tap = idx >> 12;
        int r   = idx & 4095;
        int ci  = r >> 6, co = r & 63;
        sW[idx] = wdc[((size_t)co * 64 + ci) * 9 + tap];
    }
    __syncthreads();

    u64 acc[32];
#pragma unroll
    for (int c = 0; c < 32; c++) acc[c] = 0ull;

#pragma unroll 1
    for (int n = 0; n < NTAP; n++) {
        int dr = n / 3 - 1, dc = n % 3 - 1;
        float offr = offset[(((size_t)b * 18 + n) * HH + i) * WW + j];
        float offc = offset[(((size_t)b * 18 + 9 + n) * HH + i) * WW + j];
        float p_r = (float)(i + 1 + dr) + offr;
        float p_c = (float)(j + 1 + dc) + offc;
        float pr = fminf(fmaxf(p_r, 0.f), 193.f);
        float pc = fminf(fmaxf(p_c, 0.f), 193.f);
        float fr = floorf(p_r), fc = floorf(p_c);
        float qr0 = fminf(fmaxf(fr,       0.f), 193.f);
        float qc0 = fminf(fmaxf(fc,       0.f), 193.f);
        float qr1 = fminf(fmaxf(fr + 1.f, 0.f), 193.f);
        float qc1 = fminf(fmaxf(fc + 1.f, 0.f), 193.f);
        float glt = (1.f + (qr0 - pr)) * (1.f + (qc0 - pc));
        float grb = (1.f - (qr1 - pr)) * (1.f - (qc1 - pc));
        float glb = (1.f + (qr0 - pr)) * (1.f - (qc1 - pc));
        float grt = (1.f - (qr1 - pr)) * (1.f + (qc0 - pc));
        int i00 = (int)qr0 * HP + (int)qc0;
        int i11 = (int)qr1 * HP + (int)qc1;
        int i01 = (int)qr0 * HP + (int)qc1;
        int i10 = (int)qr1 * HP + (int)qc0;

        const float* xb = xpad + (size_t)b * 64 * HP * HP;
        const float* wn = &sW[n * 4096];
#pragma unroll 1
        for (int ci = 0; ci < 64; ci++) {
            const float* xc = xb + (size_t)ci * HP * HP;
            float xo = glt * xc[i00] + grb * xc[i11]
                     + glb * xc[i01] + grt * xc[i10];
            u64 x2 = dup2(xo);
            const ulonglong2* wp = reinterpret_cast<const ulonglong2*>(&wn[ci * 64]);
#pragma unroll
            for (int jj = 0; jj < 16; jj++) {
                ulonglong2 q = wp[jj];
                fma2(acc[2 * jj],     x2, q.x);
                fma2(acc[2 * jj + 1], x2, q.y);
            }
        }
    }

    size_t obase = (size_t)b * 64 * HH * WW + (size_t)i * WW + j;
#pragma unroll
    for (int jj = 0; jj < 32; jj++) {
        float2 v = unpk(acc[jj]);
        out[obase + (size_t)(2 * jj)     * HH * WW] = v.x;
        out[obase + (size_t)(2 * jj + 1) * HH * WW] = v.y;
    }
}

// ---------------- GDN + celu (in place), FFMA2 -------------------------------
__global__ void __launch_bounds__(256, 1)
gdn_celu_kernel(float* __restrict__ x, const float* __restrict__ beta,
                const float* __restrict__ gamma, int HWp)
{
    __shared__ __align__(16) float sG[64 * 64];  // sG[ci*64+co] = gamma[co][ci]
    __shared__ float sB[64];
    const int tid = threadIdx.x;
    for (int idx = tid; idx < 4096; idx += 256) {
        int co = idx & 63, ci = idx >> 6;
        sG[idx] = gamma[co * 64 + ci];
    }
    if (tid < 64) sB[tid] = beta[tid];
    __syncthreads();

    int p = blockIdx.x * 256 + tid;
    if (p >= BB * HWp) return;
    int b = p / HWp, hw = p % HWp;
    float* base = x + (size_t)b * 64 * HWp + hw;

    u64 nrm[32];
#pragma unroll
    for (int jj = 0; jj < 32; jj++) nrm[jj] = pk2(sB[2 * jj], sB[2 * jj + 1]);

    for (int ci = 0; ci < 64; ci++) {
        float v = base[(size_t)ci * HWp];
        u64 sq = dup2(v * v);
        const ulonglong2* gp = reinterpret_cast<const ulonglong2*>(&sG[ci * 64]);
#pragma unroll
        for (int jj = 0; jj < 16; jj++) {
            ulonglong2 q = gp[jj];
            fma2(nrm[2 * jj],     sq, q.x);
            fma2(nrm[2 * jj + 1], sq, q.y);
        }
    }
#pragma unroll
    for (int jj = 0; jj < 32; jj++) {
        float2 nv = unpk(nrm[jj]);
        float v0 = base[(size_t)(2 * jj) * HWp];
        float v1 = base[(size_t)(2 * jj + 1) * HWp];
        float t0 = v0 * rsqrtf(nv.x);
        float t1 = v1 * rsqrtf(nv.y);
        base[(size_t)(2 * jj) * HWp]     = (t0 > 0.f) ? t0 : expm1f(t0);
        base[(size_t)(2 * jj + 1) * HWp] = (t1 > 0.f) ? t1 : expm1f(t1);
    }
}

// ---------------- final add --------------------------------------------------
__global__ void add_kernel(const float* __restrict__ a, const float* __restrict__ b,
                           float* __restrict__ out, int n)
{
    int i = blockIdx.x * blockDim.x + threadIdx.x;
    if (i < n) out[i] = a[i] + b[i];
}

// ---------------- launcher ---------------------------------------------------
extern "C" void kernel_launch(void* const* d_in, const int* in_sizes, int n_in,
                              void* d_out, int out_size)
{
    const float* f_r     = (const float*)d_in[0];
    const float* m_t     = (const float*)d_in[1];
    const float* w_pconv = (const float*)d_in[2];
    const float* b_pconv = (const float*)d_in[3];
    const float* w_dc    = (const float*)d_in[4];
    const float* w_cat   = (const float*)d_in[5];
    const float* b_cat   = (const float*)d_in[6];
    const float* rb_w1   = (const float*)d_in[7];
    const float* rb_w2   = (const float*)d_in[8];
    const float* rb_beta = (const float*)d_in[9];
    const float* rb_gamma= (const float*)d_in[10];
    float* out = (float*)d_out;

    float *frpad, *offs, *xbuf, *ybuf, *t1;
    cudaGetSymbolAddress((void**)&frpad, g_frpad);
    cudaGetSymbolAddress((void**)&offs,  g_offset);
    cudaGetSymbolAddress((void**)&xbuf,  g_x);
    cudaGetSymbolAddress((void**)&ybuf,  g_y);
    cudaGetSymbolAddress((void**)&t1,    g_t1);

    const int conv_smem = CONV_SMEM_FLOATS * 4;   // 78336 B
    const int def_smem  = DEF_SMEM_FLOATS  * 4;   // 147456 B
    cudaFuncSetAttribute(conv3x3_f2_kernel<128, 1, true>,
                         cudaFuncAttributeMaxDynamicSharedMemorySize, conv_smem);
    cudaFuncSetAttribute(conv3x3_f2_kernel<64, 0, false>,
                         cudaFuncAttributeMaxDynamicSharedMemorySize, conv_smem);
    cudaFuncSetAttribute(conv3x3_f2_kernel<64, 2, false>,
                         cudaFuncAttributeMaxDynamicSharedMemorySize, conv_smem);
    cudaFuncSetAttribute(deform_f2_kernel,
                         cudaFuncAttributeMaxDynamicSharedMemorySize, def_smem);

    // 1. pad f_r
    {
        int total = BB * CC * HP * HP;
        pad_kernel<<<(total + 255) / 256, 256>>>(f_r, frpad);
    }
    // 2. offset = pconv(m_t), pad 1, 64->18
    {
        dim3 grid(12, 12, BB);
        conv3x3_kernel<64, 18, 1, false><<<grid, 256>>>(
            m_t, nullptr, w_pconv, b_pconv, nullptr, offs, HH, WW, HH, WW);
    }
    // 3. x = deform_conv(f_r, offset, w_dc)
    {
        dim3 grid(6, 12, BB);
        deform_f2_kernel<<<grid, 512, def_smem>>>(frpad, offs, w_dc, xbuf);
    }
    // 4. y = conv(cat[x, f_r]), pad 1, 128->64
    {
        dim3 grid(6, 12, BB);
        conv3x3_f2_kernel<128, 1, true><<<grid, 512, conv_smem>>>(
            xbuf, f_r, w_cat, b_cat, nullptr, ybuf, HH, WW, HH, WW);
    }
    // 5. resblocks
    for (int l = 0; l < 3; l++) {
        const float* w1 = rb_w1 + (size_t)l * 64 * 64 * 9;
        const float* w2 = rb_w2 + (size_t)l * 64 * 64 * 9;
        const float* bt = rb_beta + (size_t)l * 64;
        const float* gm = rb_gamma + (size_t)l * 64 * 64;
        // conv1: pad 0, 192 -> 190
        {
            dim3 grid(6, 12, BB);
            conv3x3_f2_kernel<64, 0, false><<<grid, 512, conv_smem>>>(
                ybuf, nullptr, w1, nullptr, nullptr, t1, HH, WW, 190, 190);
        }
        // gdn + celu in place on t1
        {
            int HWp = 190 * 190;
            int total = BB * HWp;
            gdn_celu_kernel<<<(total + 255) / 256, 256>>>(t1, bt, gm, HWp);
        }
        // conv2: pad 2, 190 -> 192, + residual y (in place into y)
        {
            dim3 grid(6, 12, BB);
            conv3x3_f2_kernel<64, 2, false><<<grid, 512, conv_smem>>>(
                t1, nullptr, w2, nullptr, ybuf, ybuf, 190, 190, HH, WW);
        }
    }
    // 6. out = y + x
    {
        int n = BB * CC * HH * WW;
        add_kernel<<<(n + 255) / 256, 256>>>(ybuf, xbuf, out, n);
    }
}

// round 9
// speedup vs baseline: 1.7418x; 1.0438x over previous
#include <cuda_runtime.h>
#include <cuda_bf16.h>
#include <math.h>
#include <stdint.h>

// Problem constants
#define BB 2
#define CC 64
#define HH 192
#define WW 192
#define HP 194   // padded
#define NTAP 9

typedef unsigned long long u64;
typedef unsigned int u32;

// ---------------- f32x2 packed helpers --------------------------------------
__device__ __forceinline__ u64 dup2(float x) {
    u64 r; asm("mov.b64 %0, {%1,%1};" : "=l"(r) : "f"(x)); return r;
}
__device__ __forceinline__ u64 pk2(float lo, float hi) {
    u64 r; asm("mov.b64 %0, {%1,%2};" : "=l"(r) : "f"(lo), "f"(hi)); return r;
}
__device__ __forceinline__ void fma2(u64 &d, u64 a, u64 b) {
    asm("fma.rn.f32x2 %0, %1, %2, %0;" : "+l"(d) : "l"(a), "l"(b));
}
__device__ __forceinline__ float2 unpk(u64 v) {
    float2 f; asm("mov.b64 {%0,%1}, %2;" : "=f"(f.x), "=f"(f.y) : "l"(v)); return f;
}

// ---------------- cp.async helpers -------------------------------------------
__device__ __forceinline__ void cpa4(u32 saddr, const void* g, int sz) {
    asm volatile("cp.async.ca.shared.global [%0], [%1], 4, %2;"
                 :: "r"(saddr), "l"(g), "r"(sz));
}
__device__ __forceinline__ void cpa_commit() {
    asm volatile("cp.async.commit_group;");
}
__device__ __forceinline__ void cpa_wait1() {
    asm volatile("cp.async.wait_group 1;");
}

// ---------------- scratch buffers (static device memory; no allocation) -----
__device__ float g_frpad[BB * CC * HP * HP];
__device__ float g_offset[BB * 18 * HH * WW];
__device__ float g_x[BB * CC * HH * WW];
__device__ float g_y[BB * CC * HH * WW];
__device__ float g_t1[BB * CC * 190 * 190];

// ---------------- pad kernel -------------------------------------------------
__global__ void pad_kernel(const float* __restrict__ src, float* __restrict__ dst) {
    int idx = blockIdx.x * blockDim.x + threadIdx.x;
    int total = BB * CC * HP * HP;
    if (idx >= total) return;
    int c2 = idx % HP;
    int r2 = (idx / HP) % HP;
    int bc = idx / (HP * HP);
    float v = 0.f;
    if (r2 >= 1 && r2 <= HH && c2 >= 1 && c2 <= WW)
        v = src[(size_t)bc * HH * WW + (r2 - 1) * WW + (c2 - 1)];
    dst[idx] = v;
}

// ---------------- generic 3x3 conv (kept for pconv, COUT=18) -----------------
template<int CIN, int COUT, int PADV, bool HAS_IN2>
__global__ void __launch_bounds__(256, 1)
conv3x3_kernel(const float* __restrict__ inA, const float* __restrict__ inB,
               const float* __restrict__ w, const float* __restrict__ bias,
               const float* __restrict__ res, float* __restrict__ out,
               int Hin, int Win, int Hout, int Wout)
{
    constexpr int CH = 8;
    constexpr int COUT_P = (COUT + 3) & ~3;
    __shared__ __align__(16) float sIn[CH][18][18];
    __shared__ __align__(16) float sW[CH * 9 * COUT_P];

    const int b   = blockIdx.z;
    const int ty0 = blockIdx.y * 16;
    const int tx0 = blockIdx.x * 16;
    const int tid = threadIdx.x;
    const int py = tid >> 4, px = tid & 15;
    const int oy = ty0 + py, ox = tx0 + px;

    float acc[COUT_P];
#pragma unroll
    for (int i = 0; i < COUT_P; i++) acc[i] = 0.f;

    const int cstride = HAS_IN2 ? 64 : CIN;

    for (int c0 = 0; c0 < CIN; c0 += CH) {
        for (int idx = tid; idx < CH * 18 * 18; idx += 256) {
            int c   = idx / (18 * 18);
            int rem = idx % (18 * 18);
            int r = rem / 18, cc = rem % 18;
            int iy = ty0 - PADV + r;
            int ix = tx0 - PADV + cc;
            float v = 0.f;
            if (iy >= 0 && iy < Hin && ix >= 0 && ix < Win) {
                int ci = c0 + c;
                const float* src = inA;
                int cl = ci;
                if (HAS_IN2 && ci >= 64) { src = inB; cl = ci - 64; }
                v = src[(((size_t)b * cstride + cl) * Hin + iy) * Win + ix];
            }
            sIn[c][r][cc] = v;
        }
        for (int idx = tid; idx < CH * 9 * COUT_P; idx += 256) {
            int co = idx % COUT_P;
            int ck = idx / COUT_P;
            int ci_l = ck / 9, k = ck % 9;
            float v = 0.f;
            if (co < COUT) v = w[((size_t)co * CIN + (c0 + ci_l)) * 9 + k];
            sW[idx] = v;
        }
        __syncthreads();

        for (int ci = 0; ci < CH; ci++) {
#pragma unroll
            for (int ky = 0; ky < 3; ky++) {
#pragma unroll
                for (int kx = 0; kx < 3; kx++) {
                    float xv = sIn[ci][py + ky][px + kx];
                    const float4* wp = reinterpret_cast<const float4*>(
                        &sW[(ci * 9 + ky * 3 + kx) * COUT_P]);
#pragma unroll
                    for (int j = 0; j < COUT_P / 4; j++) {
                        float4 w4 = wp[j];
                        acc[4 * j + 0] = fmaf(w4.x, xv, acc[4 * j + 0]);
                        acc[4 * j + 1] = fmaf(w4.y, xv, acc[4 * j + 1]);
                        acc[4 * j + 2] = fmaf(w4.z, xv, acc[4 * j + 2]);
                        acc[4 * j + 3] = fmaf(w4.w, xv, acc[4 * j + 3]);
                    }
                }
            }
        }
        __syncthreads();
    }

    if (oy < Hout && ox < Wout) {
        size_t obase = (size_t)b * COUT * Hout * Wout + (size_t)oy * Wout + ox;
        size_t cs = (size_t)Hout * Wout;
#pragma unroll
        for (int co = 0; co < COUT; co++) {
            float v = acc[co];
            if (bias) v += bias[co];
            if (res)  v += res[obase + co * cs];
            out[obase + co * cs] = v;
        }
    }
}

// ---------------- FFMA2 3x3 conv, COUT=64, cp.async, division-free staging ---
// 512 threads = 2 cout-halves x 256. Each thread: 1x2 pixel pair x 32 couts.
// Tile 16x32. 2-stage cp.async pipeline; staging addresses are precomputed
// per-thread spatial positions (div/mod hoisted out of the chunk loop),
// channel loop is pure pointer increments.
// Dynamic SMEM float layout:
//   IN(buf)=buf*5184 : [CH][18][36] (34 cols used)
//   W(buf) =10368+buf*4608 : [CH][9][64]
#define CONV_SMEM_FLOATS (2*5184 + 2*4608)
template<int CIN, int PADV, bool HAS_IN2>
__global__ void __launch_bounds__(512, 1)
conv3x3_f2_kernel(const float* __restrict__ inA, const float* __restrict__ inB,
                  const float* __restrict__ w, const float* __restrict__ bias,
                  const float* __restrict__ res, const float* __restrict__ res2,
                  float* __restrict__ out,
                  int Hin, int Win, int Hout, int Wout)
{
    constexpr int CH = 8;
    constexpr int NC = CIN / CH;
    extern __shared__ __align__(16) float sm[];

    const int b   = blockIdx.z;
    const int ty0 = blockIdx.y * 16;
    const int tx0 = blockIdx.x * 32;
    const int tid = threadIdx.x;
    const int g   = tid >> 8;          // cout half
    const int t   = tid & 255;
    const int qy  = t >> 4;            // 0..15 output row
    const int qx  = t & 15;            // 0..15 output col pair

    const int cstride = HAS_IN2 ? 64 : CIN;
    const int HinWin = Hin * Win;
    const u32 smem_base = (u32)__cvta_generic_to_shared(sm);

    // ---- hoisted staging geometry (chunk-invariant) ----
    // input positions: p in [0, 18*34); thread owns p0=tid, p1=tid+512 (tid<100)
    const int p0 = tid;
    const int r0 = p0 / 34, q0 = p0 % 34;
    const int iy0 = ty0 - PADV + r0, ix0 = tx0 - PADV + q0;
    const bool ok0 = (iy0 >= 0 && iy0 < Hin && ix0 >= 0 && ix0 < Win);
    const int go0 = iy0 * Win + ix0;
    const u32 so0 = (u32)((r0 * 36 + q0) * 4);
    const int p1 = tid + 512;
    const bool has1 = (p1 < 612);
    const int r1 = p1 / 34, q1 = p1 % 34;
    const int iy1 = ty0 - PADV + r1, ix1 = tx0 - PADV + q1;
    const bool ok1 = has1 && (iy1 >= 0 && iy1 < Hin && ix1 >= 0 && ix1 < Win);
    const int go1 = iy1 * Win + ix1;
    const u32 so1 = (u32)((r1 * 36 + q1) * 4);
    // weights: thread owns co=tid&63, pair index wp0=tid>>6, steps of 8 (9 iters)
    const int wco = tid & 63;
    const int wp0 = tid >> 6;
    const size_t wbase0 = (size_t)wco * CIN * 9 + wp0;

    auto stage = [&](int buf, int cc0_) {
        const float* srcb;
        if (HAS_IN2 && cc0_ >= 64)
            srcb = inB + ((size_t)b * 64 + (cc0_ - 64)) * HinWin;
        else
            srcb = inA + ((size_t)b * cstride + cc0_) * HinWin;
        const u32 sbase = smem_base + (u32)(buf * 5184 * 4);
        {
            const float* gp = ok0 ? (srcb + go0) : srcb;
            const int step = ok0 ? HinWin : 0;
            const int sz = ok0 ? 4 : 0;
            u32 sa = sbase + so0;
#pragma unroll
            for (int c = 0; c < CH; c++) {
                cpa4(sa, gp, sz);
                gp += step; sa += 648 * 4;
            }
        }
        if (has1) {
            const float* gp = ok1 ? (srcb + go1) : srcb;
            const int step = ok1 ? HinWin : 0;
            const int sz = ok1 ? 4 : 0;
            u32 sa = sbase + so1;
#pragma unroll
            for (int c = 0; c < CH; c++) {
                cpa4(sa, gp, sz);
                gp += step; sa += 648 * 4;
            }
        }
        {
            const float* gp = w + wbase0 + (size_t)cc0_ * 9;
            u32 sa = smem_base + (u32)((10368 + buf * 4608 + wp0 * 64 + wco) * 4);
#pragma unroll
            for (int m = 0; m < 9; m++) {
                cpa4(sa, gp, 4);
                gp += 8; sa += 2048;   // 8 pairs * 64 floats * 4B
            }
        }
    };

    u64 acc[2][16];
#pragma unroll
    for (int p = 0; p < 2; p++)
#pragma unroll
        for (int j = 0; j < 16; j++) acc[p][j] = 0ull;

    // prologue: stage chunk 0
    stage(0, 0);
    cpa_commit();

    for (int c = 0; c < NC; c++) {
        int buf = c & 1;
        if (c + 1 < NC) stage(buf ^ 1, (c + 1) * CH);
        cpa_commit();
        cpa_wait1();
        __syncthreads();

        const float* sIn = sm + buf * 5184;          // [CH][18][36]
        const float* sW  = sm + 10368 + buf * 4608;  // [CH][9][64]

#pragma unroll 1
        for (int ci = 0; ci < CH; ci++) {
            u64 d[3][4];
#pragma unroll
            for (int r = 0; r < 3; r++) {
                const float2* ip = reinterpret_cast<const float2*>(
                    &sIn[(ci * 18 + qy + r) * 36 + 2 * qx]);
                float2 a = ip[0], bb = ip[1];
                d[r][0] = dup2(a.x); d[r][1] = dup2(a.y);
                d[r][2] = dup2(bb.x); d[r][3] = dup2(bb.y);
            }
#pragma unroll
            for (int ky = 0; ky < 3; ky++) {
#pragma unroll
                for (int kx = 0; kx < 3; kx++) {
                    u64 xv0 = d[ky][kx];
                    u64 xv1 = d[ky][kx + 1];
                    const ulonglong2* wp = reinterpret_cast<const ulonglong2*>(
                        &sW[(ci * 9 + ky * 3 + kx) * 64 + g * 32]);
#pragma unroll
                    for (int j = 0; j < 8; j++) {
                        ulonglong2 q = wp[j];
                        fma2(acc[0][2 * j],     xv0, q.x);
                        fma2(acc[0][2 * j + 1], xv0, q.y);
                        fma2(acc[1][2 * j],     xv1, q.x);
                        fma2(acc[1][2 * j + 1], xv1, q.y);
                    }
                }
            }
        }
        __syncthreads();
    }

    // store
    size_t cs = (size_t)Hout * Wout;
    int oy = ty0 + qy;
#pragma unroll
    for (int pc = 0; pc < 2; pc++) {
        int ox = tx0 + 2 * qx + pc;
        if (oy < Hout && ox < Wout) {
            size_t base = (size_t)b * 64 * cs + (size_t)oy * Wout + ox;
            u64* ac = acc[pc];
#pragma unroll
            for (int j = 0; j < 16; j++) {
                float2 v = unpk(ac[j]);
                int co = g * 32 + 2 * j;
                float o0 = v.x, o1 = v.y;
                if (bias) { o0 += bias[co]; o1 += bias[co + 1]; }
                if (res)  { o0 += res[base + (size_t)co * cs];
                            o1 += res[base + (size_t)(co + 1) * cs]; }
                if (res2) { o0 += res2[base + (size_t)co * cs];
                            o1 += res2[base + (size_t)(co + 1) * cs]; }
                out[base + (size_t)co * cs]       = o0;
                out[base + (size_t)(co + 1) * cs] = o1;
            }
        }
    }
}

// ---------------- deformable conv, FFMA2, all-tap weights in SMEM ------------
#define DEF_SMEM_FLOATS (9 * 64 * 64)
__global__ void __launch_bounds__(512, 1)
deform_f2_kernel(const float* __restrict__ xpad,    // (B,64,194,194)
                 const float* __restrict__ offset,  // (B,18,192,192)
                 const float* __restrict__ wdc,     // (64,64,3,3)
                 float* __restrict__ out)           // (B,64,192,192)
{
    extern __shared__ __align__(16) float sW[];     // [tap][ci][co]

    const int b   = blockIdx.z;
    const int ty0 = blockIdx.y * 16;
    const int tx0 = blockIdx.x * 32;
    const int tid = threadIdx.x;
    const int py  = tid >> 5, px = tid & 31;
    const int i   = ty0 + py;
    const int j   = tx0 + px;

    for (int idx = tid; idx < 9 * 64 * 64; idx += 512) {
        int tap = idx >> 12;
        int r   = idx & 4095;
        int ci  = r >> 6, co = r & 63;
        sW[idx] = wdc[((size_t)co * 64 + ci) * 9 + tap];
    }
    __syncthreads();

    u64 acc[32];
#pragma unroll
    for (int c = 0; c < 32; c++) acc[c] = 0ull;

#pragma unroll 1
    for (int n = 0; n < NTAP; n++) {
        int dr = n / 3 - 1, dc = n % 3 - 1;
        float offr = offset[(((size_t)b * 18 + n) * HH + i) * WW + j];
        float offc = offset[(((size_t)b * 18 + 9 + n) * HH + i) * WW + j];
        float p_r = (float)(i + 1 + dr) + offr;
        float p_c = (float)(j + 1 + dc) + offc;
        float pr = fminf(fmaxf(p_r, 0.f), 193.f);
        float pc = fminf(fmaxf(p_c, 0.f), 193.f);
        float fr = floorf(p_r), fc = floorf(p_c);
        float qr0 = fminf(fmaxf(fr,       0.f), 193.f);
        float qc0 = fminf(fmaxf(fc,       0.f), 193.f);
        float qr1 = fminf(fmaxf(fr + 1.f, 0.f), 193.f);
        float qc1 = fminf(fmaxf(fc + 1.f, 0.f), 193.f);
        float glt = (1.f + (qr0 - pr)) * (1.f + (qc0 - pc));
        float grb = (1.f - (qr1 - pr)) * (1.f - (qc1 - pc));
        float glb = (1.f + (qr0 - pr)) * (1.f - (qc1 - pc));
        float grt = (1.f - (qr1 - pr)) * (1.f + (qc0 - pc));
        int i00 = (int)qr0 * HP + (int)qc0;
        int i11 = (int)qr1 * HP + (int)qc1;
        int i01 = (int)qr0 * HP + (int)qc1;
        int i10 = (int)qr1 * HP + (int)qc0;

        const float* xb = xpad + (size_t)b * 64 * HP * HP;
        const float* wn = &sW[n * 4096];
#pragma unroll 1
        for (int ci = 0; ci < 64; ci++) {
            const float* xc = xb + (size_t)ci * HP * HP;
            float xo = glt * xc[i00] + grb * xc[i11]
                     + glb * xc[i01] + grt * xc[i10];
            u64 x2 = dup2(xo);
            const ulonglong2* wp = reinterpret_cast<const ulonglong2*>(&wn[ci * 64]);
#pragma unroll
            for (int jj = 0; jj < 16; jj++) {
                ulonglong2 q = wp[jj];
                fma2(acc[2 * jj],     x2, q.x);
                fma2(acc[2 * jj + 1], x2, q.y);
            }
        }
    }

    size_t obase = (size_t)b * 64 * HH * WW + (size_t)i * WW + j;
#pragma unroll
    for (int jj = 0; jj < 32; jj++) {
        float2 v = unpk(acc[jj]);
        out[obase + (size_t)(2 * jj)     * HH * WW] = v.x;
        out[obase + (size_t)(2 * jj + 1) * HH * WW] = v.y;
    }
}

// ---------------- GDN + celu (in place), FFMA2 -------------------------------
__global__ void __launch_bounds__(256, 1)
gdn_celu_kernel(float* __restrict__ x, const float* __restrict__ beta,
                const float* __restrict__ gamma, int HWp)
{
    __shared__ __align__(16) float sG[64 * 64];  // sG[ci*64+co] = gamma[co][ci]
    __shared__ float sB[64];
    const int tid = threadIdx.x;
    for (int idx = tid; idx < 4096; idx += 256) {
        int co = idx & 63, ci = idx >> 6;
        sG[idx] = gamma[co * 64 + ci];
    }
    if (tid < 64) sB[tid] = beta[tid];
    __syncthreads();

    int p = blockIdx.x * 256 + tid;
    if (p >= BB * HWp) return;
    int b = p / HWp, hw = p % HWp;
    float* base = x + (size_t)b * 64 * HWp + hw;

    u64 nrm[32];
#pragma unroll
    for (int jj = 0; jj < 32; jj++) nrm[jj] = pk2(sB[2 * jj], sB[2 * jj + 1]);

    for (int ci = 0; ci < 64; ci++) {
        float v = base[(size_t)ci * HWp];
        u64 sq = dup2(v * v);
        const ulonglong2* gp = reinterpret_cast<const ulonglong2*>(&sG[ci * 64]);
#pragma unroll
        for (int jj = 0; jj < 16; jj++) {
            ulonglong2 q = gp[jj];
            fma2(nrm[2 * jj],     sq, q.x);
            fma2(nrm[2 * jj + 1], sq, q.y);
        }
    }
#pragma unroll
    for (int jj = 0; jj < 32; jj++) {
        float2 nv = unpk(nrm[jj]);
        float v0 = base[(size_t)(2 * jj) * HWp];
        float v1 = base[(size_t)(2 * jj + 1) * HWp];
        float t0 = v0 * rsqrtf(nv.x);
        float t1 = v1 * rsqrtf(nv.y);
        base[(size_t)(2 * jj) * HWp]     = (t0 > 0.f) ? t0 : expm1f(t0);
        base[(size_t)(2 * jj + 1) * HWp] = (t1 > 0.f) ? t1 : expm1f(t1);
    }
}

// ---------------- launcher ---------------------------------------------------
extern "C" void kernel_launch(void* const* d_in, const int* in_sizes, int n_in,
                              void* d_out, int out_size)
{
    const float* f_r     = (const float*)d_in[0];
    const float* m_t     = (const float*)d_in[1];
    const float* w_pconv = (const float*)d_in[2];
    const float* b_pconv = (const float*)d_in[3];
    const float* w_dc    = (const float*)d_in[4];
    const float* w_cat   = (const float*)d_in[5];
    const float* b_cat   = (const float*)d_in[6];
    const float* rb_w1   = (const float*)d_in[7];
    const float* rb_w2   = (const float*)d_in[8];
    const float* rb_beta = (const float*)d_in[9];
    const float* rb_gamma= (const float*)d_in[10];
    float* out = (float*)d_out;

    float *frpad, *offs, *xbuf, *ybuf, *t1;
    cudaGetSymbolAddress((void**)&frpad, g_frpad);
    cudaGetSymbolAddress((void**)&offs,  g_offset);
    cudaGetSymbolAddress((void**)&xbuf,  g_x);
    cudaGetSymbolAddress((void**)&ybuf,  g_y);
    cudaGetSymbolAddress((void**)&t1,    g_t1);

    const int conv_smem = CONV_SMEM_FLOATS * 4;   // 78336 B
    const int def_smem  = DEF_SMEM_FLOATS  * 4;   // 147456 B
    cudaFuncSetAttribute(conv3x3_f2_kernel<128, 1, true>,
                         cudaFuncAttributeMaxDynamicSharedMemorySize, conv_smem);
    cudaFuncSetAttribute(conv3x3_f2_kernel<64, 0, false>,
                         cudaFuncAttributeMaxDynamicSharedMemorySize, conv_smem);
    cudaFuncSetAttribute(conv3x3_f2_kernel<64, 2, false>,
                         cudaFuncAttributeMaxDynamicSharedMemorySize, conv_smem);
    cudaFuncSetAttribute(deform_f2_kernel,
                         cudaFuncAttributeMaxDynamicSharedMemorySize, def_smem);

    // 1. pad f_r
    {
        int total = BB * CC * HP * HP;
        pad_kernel<<<(total + 255) / 256, 256>>>(f_r, frpad);
    }
    // 2. offset = pconv(m_t), pad 1, 64->18
    {
        dim3 grid(12, 12, BB);
        conv3x3_kernel<64, 18, 1, false><<<grid, 256>>>(
            m_t, nullptr, w_pconv, b_pconv, nullptr, offs, HH, WW, HH, WW);
    }
    // 3. x = deform_conv(f_r, offset, w_dc)
    {
        dim3 grid(6, 12, BB);
        deform_f2_kernel<<<grid, 512, def_smem>>>(frpad, offs, w_dc, xbuf);
    }
    // 4. y = conv(cat[x, f_r]), pad 1, 128->64
    {
        dim3 grid(6, 12, BB);
        conv3x3_f2_kernel<128, 1, true><<<grid, 512, conv_smem>>>(
            xbuf, f_r, w_cat, b_cat, nullptr, nullptr, ybuf, HH, WW, HH, WW);
    }
    // 5. resblocks
    for (int l = 0; l < 3; l++) {
        const float* w1 = rb_w1 + (size_t)l * 64 * 64 * 9;
        const float* w2 = rb_w2 + (size_t)l * 64 * 64 * 9;
        const float* bt = rb_beta + (size_t)l * 64;
        const float* gm = rb_gamma + (size_t)l * 64 * 64;
        // conv1: pad 0, 192 -> 190
        {
            dim3 grid(6, 12, BB);
            conv3x3_f2_kernel<64, 0, false><<<grid, 512, conv_smem>>>(
                ybuf, nullptr, w1, nullptr, nullptr, nullptr, t1, HH, WW, 190, 190);
        }
        // gdn + celu in place on t1
        {
            int HWp = 190 * 190;
            int total = BB * HWp;
            gdn_celu_kernel<<<(total + 255) / 256, 256>>>(t1, bt, gm, HWp);
        }
        // conv2: pad 2, 190 -> 192, + residual y.
        // Last layer: also add x (res2) and write straight to harness output.
        {
            dim3 grid(6, 12, BB);
            if (l < 2) {
                conv3x3_f2_kernel<64, 2, false><<<grid, 512, conv_smem>>>(
                    t1, nullptr, w2, nullptr, ybuf, nullptr, ybuf, 190, 190, HH, WW);
            } else {
                conv3x3_f2_kernel<64, 2, false><<<grid, 512, conv_smem>>>(
                    t1, nullptr, w2, nullptr, ybuf, xbuf, out, 190, 190, HH, WW);
            }
        }
    }
}